// round 15
// baseline (speedup 1.0000x reference)
#include <cuda_runtime.h>

#define FULLMASK 0xffffffffu
typedef unsigned long long u64;

// ---------------------------------------------------------------------------
// ONE SAMPLE PER WARP (back from 2/warp: state drops 32->16 regs, lifting the
// occupancy ceiling 50% -> 75%; R8-R14 showed dur ~ 1/occ with no pipe
// saturated). Keeps all later wins: fused 1q chains, CE-packed matrices,
// 3-shape CSWAP, per-block shared GateTab, single kernel launch.
// Amplitude index i (8 bits) = (r << 5) | lane. wire w <-> bit (7-w).
// Bits 0..4 = lane bits, 5..7 = register bits. a[8] packed complex (re,im).
// ---------------------------------------------------------------------------

constexpr int LB = 5;   // number of lane bits

__device__ __forceinline__ u64 pack2(float lo, float hi) {
    u64 r; asm("mov.b64 %0, {%1, %2};" : "=l"(r) : "f"(lo), "f"(hi)); return r;
}
__device__ __forceinline__ void unpack2(u64 v, float& lo, float& hi) {
    asm("mov.b64 {%0, %1}, %2;" : "=f"(lo), "=f"(hi) : "l"(v));
}
__device__ __forceinline__ u64 dup2(float x) { return pack2(x, x); }
__device__ __forceinline__ u64 fma2(u64 a, u64 b, u64 c) {
    u64 d; asm("fma.rn.f32x2 %0, %1, %2, %3;" : "=l"(d) : "l"(a), "l"(b), "l"(c)); return d;
}
__device__ __forceinline__ u64 mul2(u64 a, u64 b) {
    u64 d; asm("mul.rn.f32x2 %0, %1, %2;" : "=l"(d) : "l"(a), "l"(b)); return d;
}
__device__ __forceinline__ u64 swap2(u64 v) {
    float lo, hi; unpack2(v, lo, hi); return pack2(hi, lo);
}
template<int ML>
__device__ __forceinline__ u64 shfl2(u64 v) {
    float lo, hi; unpack2(v, lo, hi);
    lo = __shfl_xor_sync(FULLMASK, lo, ML);
    hi = __shfl_xor_sync(FULLMASK, hi, ML);
    return pack2(lo, hi);
}

// ------------------------- fused 1q applies ---------------------------------

// Real 2x2 [u00,u01;u10,u11].
template<int B>
__device__ __forceinline__ void ap_real(u64 a[8], int lane,
                                        float u00, float u01, float u10, float u11) {
    if constexpr (B >= LB) {
        constexpr int M = 1 << (B - LB);
        u64 c00 = dup2(u00), c01 = dup2(u01), c10 = dup2(u10), c11 = dup2(u11);
#pragma unroll
        for (int r = 0; r < 8; r++) {
            if ((r & M) == 0) {
                int r1 = r | M;
                u64 v0 = a[r], v1 = a[r1];
                a[r]  = fma2(c01, v1, mul2(c00, v0));
                a[r1] = fma2(c11, v1, mul2(c10, v0));
            }
        }
    } else {
        int bit = (lane >> B) & 1;
        u64 u = dup2(bit ? u11 : u00);
        u64 v = dup2(bit ? u10 : u01);
#pragma unroll
        for (int r = 0; r < 8; r++) {
            u64 p = shfl2<(1 << B)>(a[r]);
            a[r] = fma2(v, p, mul2(u, a[r]));
        }
    }
}

// Complex 2x2 in CE form: per entry r2=(re,re), i2=(-im,im).
template<int B>
__device__ __forceinline__ void ap_cplx_ce(u64 a[8], int lane,
        u64 r00, u64 i00, u64 r01, u64 i01,
        u64 r10, u64 i10, u64 r11, u64 i11) {
    if constexpr (B >= LB) {
        constexpr int M = 1 << (B - LB);
#pragma unroll
        for (int r = 0; r < 8; r++) {
            if ((r & M) == 0) {
                int r1 = r | M;
                u64 v0 = a[r], v1 = a[r1];
                u64 s0 = swap2(v0), s1 = swap2(v1);
                a[r]  = fma2(i01, s1, fma2(r01, v1, fma2(i00, s0, mul2(r00, v0))));
                a[r1] = fma2(i11, s1, fma2(r11, v1, fma2(i10, s0, mul2(r10, v0))));
            }
        }
    } else {
        int bit = (lane >> B) & 1;
        u64 ur = bit ? r11 : r00, ui = bit ? i11 : i00;
        u64 vr = bit ? r10 : r01, vi = bit ? i10 : i01;
#pragma unroll
        for (int r = 0; r < 8; r++) {
            u64 p = shfl2<(1 << B)>(a[r]);
            u64 t = fma2(ui, swap2(a[r]), mul2(ur, a[r]));
            a[r] = fma2(vi, swap2(p), fma2(vr, p, t));
        }
    }
}

// Diagonal complex (CE form d0, d1) — zero shuffles.
template<int B>
__device__ __forceinline__ void ap_diag_ce(u64 a[8], int lane,
                                           u64 r0, u64 i0, u64 r1, u64 i1) {
    if constexpr (B >= LB) {
        constexpr int M = 1 << (B - LB);
#pragma unroll
        for (int r = 0; r < 8; r++) {
            u64 rr = (r & M) ? r1 : r0;
            u64 ii = (r & M) ? i1 : i0;
            a[r] = fma2(ii, swap2(a[r]), mul2(rr, a[r]));
        }
    } else {
        int bit = (lane >> B) & 1;
        u64 rr = bit ? r1 : r0, ii = bit ? i1 : i0;
#pragma unroll
        for (int r = 0; r < 8; r++)
            a[r] = fma2(ii, swap2(a[r]), mul2(rr, a[r]));
    }
}

// ------------------------- multi-qubit gates --------------------------------

// Controlled-X: flip bit T where all CM bits set. CM==0 -> plain X.
template<int T, int CM>
__device__ __forceinline__ void g_cx(u64 a[8], int lane) {
    constexpr int CML = CM & ((1 << LB) - 1);
    constexpr int CMR = (CM >> LB) & 7;
    bool lp = ((lane & CML) == CML);
    if constexpr (T < LB) {
#pragma unroll
        for (int r = 0; r < 8; r++) {
            if ((r & CMR) == CMR) {
                u64 p = shfl2<(1 << T)>(a[r]);
                if constexpr (CML == 0) a[r] = p;
                else a[r] = lp ? p : a[r];
            }
        }
    } else {
        constexpr int MT = 1 << (T - LB);
#pragma unroll
        for (int r = 0; r < 8; r++) {
            if (((r & CMR) == CMR) && !(r & MT)) {
                int r1 = r | MT;
                u64 v0 = a[r], v1 = a[r1];
                if constexpr (CML == 0) { a[r] = v1; a[r1] = v0; }
                else { a[r] = lp ? v1 : v0; a[r1] = lp ? v0 : v1; }
            }
        }
    }
}

// CZ on bits BA, BB
template<int BA, int BB>
__device__ __forceinline__ void g_cz(u64 a[8], int lane) {
    bool lp = true;
    if constexpr (BA < LB) lp = lp && (((lane >> BA) & 1) != 0);
    if constexpr (BB < LB) lp = lp && (((lane >> BB) & 1) != 0);
    u64 sg = dup2(lp ? -1.f : 1.f);
#pragma unroll
    for (int r = 0; r < 8; r++) {
        bool rp = true;
        if (BA >= LB) rp = rp && (((r >> (BA - LB)) & 1) != 0);
        if (BB >= LB) rp = rp && (((r >> (BB - LB)) & 1) != 0);
        if (rp) a[r] = mul2(sg, a[r]);
    }
}

// Static prune: no swap possible for this r.
template<int A, int Bb, int C>
__device__ __forceinline__ constexpr bool cswap_possible(int r) {
    bool possible = true;
    if (C >= LB && !((r >> (C - LB)) & 1)) possible = false;
    if (A >= LB && Bb >= LB &&
        (((r >> (A - LB)) & 1) == ((r >> (Bb - LB)) & 1))) possible = false;
    return possible;
}

// Swap condition for element (r, lane).
template<int A, int Bb, int C>
__device__ __forceinline__ bool cswap_cond(int r, int lane, bool lctl) {
    int ba = (A  < LB) ? ((lane >> A)  & 1) : ((r >> (A  - LB)) & 1);
    int bb = (Bb < LB) ? ((lane >> Bb) & 1) : ((r >> (Bb - LB)) & 1);
    bool ctl = (C < LB) ? lctl : (((r >> (C - LB)) & 1) != 0);
    return ctl && (ba != bb);
}

// CSWAP: control C; swap bits A,Bb where they differ. Three static shapes.
template<int A, int Bb, int C>
__device__ __forceinline__ void g_cswap(u64 a[8], int lane) {
    constexpr int M  = (1 << A) | (1 << Bb);
    constexpr int ML = M & ((1 << LB) - 1);
    constexpr int MR = (M >> LB) & 7;
    bool lctl = true;
    if constexpr (C < LB) lctl = (((lane >> C) & 1) != 0);

    if constexpr (MR == 0) {
        // (1) both swap bits lane bits: element-wise shuffle select.
#pragma unroll
        for (int r = 0; r < 8; r++) {
            if (cswap_possible<A, Bb, C>(r)) {
                u64 p = shfl2<ML>(a[r]);
                bool sw = cswap_cond<A, Bb, C>(r, lane, lctl);
                a[r] = sw ? p : a[r];
            }
        }
    } else if constexpr (ML != 0) {
        // (2) one register + one lane bit: closed pairs (r, r|MR).
#pragma unroll
        for (int r = 0; r < 8; r++) {
            if ((r & MR) == 0) {
                int r1 = r | MR;
                bool pos0 = cswap_possible<A, Bb, C>(r);
                bool pos1 = cswap_possible<A, Bb, C>(r | MR);
                u64 p0s = a[r1], p1s = a[r];     // read both before any write
                if (pos0) {
                    u64 p0 = shfl2<ML>(p0s);
                    bool sw0 = cswap_cond<A, Bb, C>(r, lane, lctl);
                    a[r] = sw0 ? p0 : a[r];
                }
                if (pos1) {
                    u64 p1 = shfl2<ML>(p1s);
                    bool sw1 = cswap_cond<A, Bb, C>(r1, lane, lctl);
                    a[r1] = sw1 ? p1 : a[r1];
                }
            }
        }
    } else {
        // (3) both register bits: pairs are (bitA=1,bitB=0) <-> r^MR.
        constexpr int MA = 1 << (A - LB);
        constexpr int MB = 1 << (Bb - LB);
#pragma unroll
        for (int r = 0; r < 8; r++) {
            if ((r & MA) != 0 && (r & MB) == 0) {
                int r1 = r ^ MR;
                bool ctl = (C < LB) ? lctl : (((r >> (C - LB)) & 1) != 0);
                u64 t0 = a[r], t1 = a[r1];
                a[r]  = ctl ? t1 : t0;
                a[r1] = ctl ? t0 : t1;
            }
        }
    }
}

// ---------------------------------------------------------------------------
// Per-block gate table in SHARED memory (5.6KB), computed by threads 0..47.
// code bits [0:3) = q1: 0 none,1 diag,2 real,3 cplx,4 ry,5 ry+diag,6 ry+real,7 ry+cplx
// code bits [3:6) = multiq: 0 none, 1 CNOT, 2 CSWAP, 3 TOF, 4 CZ.
// ---------------------------------------------------------------------------
struct GateTab {
    ulonglong2 ce[192];     // CE form entries (r2, i2) per matrix element
    ulonglong2 raw[96];     // packed (re,im) rows for runtime RY folding
    float4 realmat[48];     // (A00r, A01r, A10r, A11r)
    int code[48];
};

struct C2 { float re, im; };
__device__ __forceinline__ C2 cxm(C2 a, C2 b) {
    C2 o; o.re = a.re * b.re - a.im * b.im; o.im = a.re * b.im + a.im * b.re; return o;
}
__device__ __forceinline__ C2 cxa(C2 a, C2 b) { C2 o; o.re = a.re + b.re; o.im = a.im + b.im; return o; }

// Fold gate chain for (layer,node) = (i>>3, i&7); write into shared tab.
__device__ void fold_gate(GateTab& tab, int i,
                          const float* __restrict__ qp,
                          const int* __restrict__ dry,
                          const int* __restrict__ drot,
                          const int* __restrict__ dg2) {
    int node = i & 7;
    int di = (i >> 3) * 4 + (node & 3);
    float s, c;
    __sincosf(0.5f * __ldg(&qp[i]), &s, &c);

    C2 A[2][2] = {{{1.f,0.f},{0.f,0.f}},{{0.f,0.f},{1.f,0.f}}};
    bool haveA = false;
    int rot = __ldg(&drot[di]);
    if (rot == 0) {
        A[0][0] = {c,0.f}; A[0][1] = {0.f,-s}; A[1][0] = {0.f,-s}; A[1][1] = {c,0.f};
        haveA = true;
    } else if (rot == 1) {
        A[0][0] = {c,0.f}; A[0][1] = {-s,0.f}; A[1][0] = {s,0.f};  A[1][1] = {c,0.f};
        haveA = true;
    } else if (rot == 2) {
        A[0][0] = {c,-s};  A[0][1] = {0.f,0.f}; A[1][0] = {0.f,0.f}; A[1][1] = {c,s};
        haveA = true;
    }
    int g2 = __ldg(&dg2[di]);
    if (g2 >= 1 && g2 <= 4) {
        const float rh = 0.70710678118654752440f;
        C2 G[2][2];
        if (g2 == 1) {
            G[0][0] = {rh,0.f}; G[0][1] = {rh,0.f}; G[1][0] = {rh,0.f}; G[1][1] = {-rh,0.f};
        } else if (g2 == 2) {
            G[0][0] = {0.f,0.f}; G[0][1] = {1.f,0.f}; G[1][0] = {1.f,0.f}; G[1][1] = {0.f,0.f};
        } else if (g2 == 3) {
            G[0][0] = {0.f,0.f}; G[0][1] = {0.f,-1.f}; G[1][0] = {0.f,1.f}; G[1][1] = {0.f,0.f};
        } else {
            G[0][0] = {1.f,0.f}; G[0][1] = {0.f,0.f}; G[1][0] = {0.f,0.f}; G[1][1] = {-1.f,0.f};
        }
        C2 R[2][2];
        for (int r = 0; r < 2; r++)
            for (int cc = 0; cc < 2; cc++)
                R[r][cc] = cxa(cxm(G[r][0], A[0][cc]), cxm(G[r][1], A[1][cc]));
        A[0][0] = R[0][0]; A[0][1] = R[0][1]; A[1][0] = R[1][0]; A[1][1] = R[1][1];
        haveA = true;
    }
    int atype = 0;
    if (haveA) {
        bool offd  = (A[0][1].re != 0.f) || (A[0][1].im != 0.f) ||
                     (A[1][0].re != 0.f) || (A[1][0].im != 0.f);
        bool anyim = (A[0][0].im != 0.f) || (A[0][1].im != 0.f) ||
                     (A[1][0].im != 0.f) || (A[1][1].im != 0.f);
        atype = offd ? (anyim ? 3 : 2) : 1;
    }
    int q1 = (__ldg(&dry[di]) & 1) ? (4 + atype) : atype;
    int mq = (g2 >= 5) ? (g2 - 4) : 0;
    tab.code[i] = q1 | (mq << 3);

    tab.raw[2 * i]     = make_ulonglong2(pack2(A[0][0].re, A[0][0].im),
                                         pack2(A[0][1].re, A[0][1].im));
    tab.raw[2 * i + 1] = make_ulonglong2(pack2(A[1][0].re, A[1][0].im),
                                         pack2(A[1][1].re, A[1][1].im));
    tab.ce[4 * i + 0] = make_ulonglong2(dup2(A[0][0].re), pack2(-A[0][0].im, A[0][0].im));
    tab.ce[4 * i + 1] = make_ulonglong2(dup2(A[0][1].re), pack2(-A[0][1].im, A[0][1].im));
    tab.ce[4 * i + 2] = make_ulonglong2(dup2(A[1][0].re), pack2(-A[1][0].im, A[1][0].im));
    tab.ce[4 * i + 3] = make_ulonglong2(dup2(A[1][1].re), pack2(-A[1][1].im, A[1][1].im));
    tab.realmat[i] = make_float4(A[0][0].re, A[0][1].re, A[1][0].re, A[1][1].re);
}

// ---------------------------------------------------------------------------

template<int NODE>
__device__ __forceinline__ void do_node(const GateTab& tab, u64 a[8], int lane,
                                        int layer, float fc_, float fs_) {
    constexpr int B  = 7 - NODE;
    constexpr int B1 = 7 - ((NODE + 1) & 7);
    constexpr int B2 = 7 - ((NODE + 2) & 7);
    const int idx = layer * 8 + NODE;

    int code = tab.code[idx];         // uniform LDS broadcast
    int q1 = code & 7;
    if (q1) {
        switch (q1) {
            case 1: {   // diag: zero shuffles
                ulonglong2 e0 = tab.ce[4 * idx];
                ulonglong2 e3 = tab.ce[4 * idx + 3];
                ap_diag_ce<B>(a, lane, e0.x, e0.y, e3.x, e3.y);
            } break;
            case 2: {   // real
                float4 m = tab.realmat[idx];
                ap_real<B>(a, lane, m.x, m.y, m.z, m.w);
            } break;
            case 3: {   // complex
                ulonglong2 e0 = tab.ce[4 * idx + 0];
                ulonglong2 e1 = tab.ce[4 * idx + 1];
                ulonglong2 e2 = tab.ce[4 * idx + 2];
                ulonglong2 e3 = tab.ce[4 * idx + 3];
                ap_cplx_ce<B>(a, lane, e0.x, e0.y, e1.x, e1.y,
                                       e2.x, e2.y, e3.x, e3.y);
            } break;
            case 4: {   // pure RY — broadcast this warp's sample angle
                float c = __shfl_sync(FULLMASK, fc_, NODE);
                float s = __shfl_sync(FULLMASK, fs_, NODE);
                ap_real<B>(a, lane, c, -s, s, c);
            } break;
            case 6: {   // RY folded into real A
                float c = __shfl_sync(FULLMASK, fc_, NODE);
                float s = __shfl_sync(FULLMASK, fs_, NODE);
                float4 m = tab.realmat[idx];
                float u00 = fmaf(m.x, c,  m.y * s);
                float u01 = fmaf(m.y, c, -m.x * s);
                float u10 = fmaf(m.z, c,  m.w * s);
                float u11 = fmaf(m.w, c, -m.z * s);
                ap_real<B>(a, lane, u00, u01, u10, u11);
            } break;
            default: {  // 5 or 7: RY folded into complex A
                float c = __shfl_sync(FULLMASK, fc_, NODE);
                float s = __shfl_sync(FULLMASK, fs_, NODE);
                ulonglong2 ra = tab.raw[2 * idx];
                ulonglong2 rb = tab.raw[2 * idx + 1];
                u64 c2 = dup2(c), s2 = dup2(s), ns2 = dup2(-s);
                u64 M00 = fma2(s2, ra.y, mul2(c2,  ra.x));
                u64 M01 = fma2(c2, ra.y, mul2(ns2, ra.x));
                u64 M10 = fma2(s2, rb.y, mul2(c2,  rb.x));
                u64 M11 = fma2(c2, rb.y, mul2(ns2, rb.x));
                float mr, mi;
                unpack2(M00, mr, mi); u64 r00 = dup2(mr), i00 = pack2(-mi, mi);
                unpack2(M01, mr, mi); u64 r01 = dup2(mr), i01 = pack2(-mi, mi);
                unpack2(M10, mr, mi); u64 r10 = dup2(mr), i10 = pack2(-mi, mi);
                unpack2(M11, mr, mi); u64 r11 = dup2(mr), i11 = pack2(-mi, mi);
                ap_cplx_ce<B>(a, lane, r00, i00, r01, i01, r10, i10, r11, i11);
            } break;
        }
    }
    int mq = (code >> 3) & 7;
    if (mq) {
        switch (mq) {
            case 1: g_cx<B1, (1 << B)>(a, lane); break;               // CNOT
            case 2: g_cswap<B1, B2, B>(a, lane); break;               // CSWAP
            case 3: g_cx<B2, (1 << B) | (1 << B1)>(a, lane); break;   // Toffoli
            default: g_cz<B, B1>(a, lane); break;                     // CZ
        }
    }
}

__global__ void __launch_bounds__(256, 6) qsim_kernel(
    const float* __restrict__ feats,   // [B, 8]
    const float* __restrict__ qp,      // [48]
    const int* __restrict__ dry,       // [24]
    const int* __restrict__ drot,      // [24]
    const int* __restrict__ dg2,       // [24]
    float* __restrict__ out,           // [B, 8]
    int batch) {
    __shared__ GateTab tab;
    if (threadIdx.x < 48)
        fold_gate(tab, threadIdx.x, qp, dry, drot, dg2);

    int w = (int)((blockIdx.x * blockDim.x + threadIdx.x) >> 5);
    int lane = threadIdx.x & 31;

    float fv = 0.f;
    if (w < batch) fv = feats[w * 8 + (lane & 7)];
    float fs_, fc_;
    __sincosf(0.5f * fv, &fs_, &fc_);

    __syncthreads();                        // table ready
    if (w >= batch) return;

    // H^8 |0...0>  ==  uniform 1/16 real amplitude
    u64 a[8];
    u64 init = pack2(0.0625f, 0.0f);
#pragma unroll
    for (int r = 0; r < 8; r++) a[r] = init;

#pragma unroll 1
    for (int layer = 0; layer < 6; ++layer) {
        do_node<0>(tab, a, lane, layer, fc_, fs_);
        do_node<1>(tab, a, lane, layer, fc_, fs_);
        do_node<2>(tab, a, lane, layer, fc_, fs_);
        do_node<3>(tab, a, lane, layer, fc_, fs_);
        do_node<4>(tab, a, lane, layer, fc_, fs_);
        do_node<5>(tab, a, lane, layer, fc_, fs_);
        do_node<6>(tab, a, lane, layer, fc_, fs_);
        do_node<7>(tab, a, lane, layer, fc_, fs_);
    }

    // <Z_p> = sum_i |a_i|^2 * (1 - 2*bit_{7-p}(i)),  i = (r<<5) | lane
    float acc[8];
#pragma unroll
    for (int p = 0; p < 8; p++) acc[p] = 0.f;
    float sgl[8];
#pragma unroll
    for (int p = 3; p < 8; p++)
        sgl[p] = ((lane >> (7 - p)) & 1) ? -1.f : 1.f;   // lane bits 4..0
#pragma unroll
    for (int r = 0; r < 8; r++) {
        float re, im;
        unpack2(a[r], re, im);
        float pr = fmaf(re, re, im * im);
        // p=0..2 -> bits 7..5 -> r bits 2..0: compile-time signs
        acc[0] += ((r >> 2) & 1) ? -pr : pr;
        acc[1] += ((r >> 1) & 1) ? -pr : pr;
        acc[2] += (r & 1)        ? -pr : pr;
#pragma unroll
        for (int p = 3; p < 8; p++) acc[p] += sgl[p] * pr;
    }
#pragma unroll
    for (int p = 0; p < 8; p++) {
#pragma unroll
        for (int off = 16; off; off >>= 1)
            acc[p] += __shfl_xor_sync(FULLMASK, acc[p], off);
    }
    if (lane == 0) {
        float4* o = reinterpret_cast<float4*>(out + (size_t)w * 8);
        o[0] = make_float4(acc[0], acc[1], acc[2], acc[3]);
        o[1] = make_float4(acc[4], acc[5], acc[6], acc[7]);
    }
}

extern "C" void kernel_launch(void* const* d_in, const int* in_sizes, int n_in,
                              void* d_out, int out_size) {
    const float* feats = (const float*)d_in[0];   // [B, 8] float32
    const float* qp    = (const float*)d_in[1];   // [48]  float32
    const int* dry     = (const int*)d_in[2];     // [6,4] int32
    const int* drot    = (const int*)d_in[3];     // [6,4] int32
    const int* dg2     = (const int*)d_in[4];     // [6,4] int32
    float* out         = (float*)d_out;           // [B, 8] float32

    int batch = in_sizes[0] / 8;                  // 1 sample per warp
    int threads = 256;
    long long total_threads = (long long)batch * 32;
    int blocks = (int)((total_threads + threads - 1) / threads);
    qsim_kernel<<<blocks, threads>>>(feats, qp, dry, drot, dg2, out, batch);
}

// round 16
// speedup vs baseline: 1.0984x; 1.0984x over previous
#include <cuda_runtime.h>

#define FULLMASK 0xffffffffu
typedef unsigned long long u64;

// ---------------------------------------------------------------------------
// TWO SAMPLES PER WARP — SINGLE KERNEL LAUNCH. (R14 base, best = 86.0us)
// Amplitude index i (8 bits) = (r << 4) | (lane & 15). Sample = 2*warp + lane>>4.
// wire w <-> bit (7-w). Bits 0..3 = lane bits, 4..7 = register bits.
// a[16] packed complex amplitudes (lo32=re, hi32=im).
// R16: select-before-fold on complex lane-bit paths — both needed entries of
// M live in row `bit`, so select the row first, fold RY into 2 entries (not
// 4), and load only 2 CE entries for pure-complex gates. Cuts ~5% instrs.
// ---------------------------------------------------------------------------

constexpr int LB = 4;   // number of lane bits

__device__ __forceinline__ u64 pack2(float lo, float hi) {
    u64 r; asm("mov.b64 %0, {%1, %2};" : "=l"(r) : "f"(lo), "f"(hi)); return r;
}
__device__ __forceinline__ void unpack2(u64 v, float& lo, float& hi) {
    asm("mov.b64 {%0, %1}, %2;" : "=f"(lo), "=f"(hi) : "l"(v));
}
__device__ __forceinline__ u64 dup2(float x) { return pack2(x, x); }
__device__ __forceinline__ u64 fma2(u64 a, u64 b, u64 c) {
    u64 d; asm("fma.rn.f32x2 %0, %1, %2, %3;" : "=l"(d) : "l"(a), "l"(b), "l"(c)); return d;
}
__device__ __forceinline__ u64 mul2(u64 a, u64 b) {
    u64 d; asm("mul.rn.f32x2 %0, %1, %2;" : "=l"(d) : "l"(a), "l"(b)); return d;
}
__device__ __forceinline__ u64 swap2(u64 v) {
    float lo, hi; unpack2(v, lo, hi); return pack2(hi, lo);
}
template<int ML>
__device__ __forceinline__ u64 shfl2(u64 v) {
    float lo, hi; unpack2(v, lo, hi);
    lo = __shfl_xor_sync(FULLMASK, lo, ML);
    hi = __shfl_xor_sync(FULLMASK, hi, ML);
    return pack2(lo, hi);
}

// ------------------------- fused 1q applies ---------------------------------

// Real 2x2 [u00,u01;u10,u11]; coefficients may differ per half-warp.
template<int B>
__device__ __forceinline__ void ap_real(u64 a[16], int lane,
                                        float u00, float u01, float u10, float u11) {
    if constexpr (B >= LB) {
        constexpr int M = 1 << (B - LB);
        u64 c00 = dup2(u00), c01 = dup2(u01), c10 = dup2(u10), c11 = dup2(u11);
#pragma unroll
        for (int r = 0; r < 16; r++) {
            if ((r & M) == 0) {
                int r1 = r | M;
                u64 v0 = a[r], v1 = a[r1];
                a[r]  = fma2(c01, v1, mul2(c00, v0));
                a[r1] = fma2(c11, v1, mul2(c10, v0));
            }
        }
    } else {
        int bit = (lane >> B) & 1;
        u64 u = dup2(bit ? u11 : u00);
        u64 v = dup2(bit ? u10 : u01);
#pragma unroll
        for (int r = 0; r < 16; r++) {
            u64 p = shfl2<(1 << B)>(a[r]);
            a[r] = fma2(v, p, mul2(u, a[r]));
        }
    }
}

// Complex 2x2 full (register-bit wires only), CE form per entry.
template<int B>
__device__ __forceinline__ void ap_cplx_reg(u64 a[16],
        u64 r00, u64 i00, u64 r01, u64 i01,
        u64 r10, u64 i10, u64 r11, u64 i11) {
    static_assert(B >= LB, "reg path only");
    constexpr int M = 1 << (B - LB);
#pragma unroll
    for (int r = 0; r < 16; r++) {
        if ((r & M) == 0) {
            int r1 = r | M;
            u64 v0 = a[r], v1 = a[r1];
            u64 s0 = swap2(v0), s1 = swap2(v1);
            a[r]  = fma2(i01, s1, fma2(r01, v1, fma2(i00, s0, mul2(r00, v0))));
            a[r1] = fma2(i11, s1, fma2(r11, v1, fma2(i10, s0, mul2(r10, v0))));
        }
    }
}

// Complex 2x2 lane-bit apply with PRE-SELECTED entries (this thread's row):
// U = M[bit][bit], V = M[bit][1-bit], CE form.
template<int B>
__device__ __forceinline__ void ap_cplx_lane(u64 a[16],
        u64 ur, u64 ui, u64 vr, u64 vi) {
    static_assert(B < LB, "lane path only");
#pragma unroll
    for (int r = 0; r < 16; r++) {
        u64 p = shfl2<(1 << B)>(a[r]);
        u64 t = fma2(ui, swap2(a[r]), mul2(ur, a[r]));
        a[r] = fma2(vi, swap2(p), fma2(vr, p, t));
    }
}

// Diagonal complex (CE form d0, d1) — zero shuffles.
template<int B>
__device__ __forceinline__ void ap_diag_ce(u64 a[16], int lane,
                                           u64 r0, u64 i0, u64 r1, u64 i1) {
    if constexpr (B >= LB) {
        constexpr int M = 1 << (B - LB);
#pragma unroll
        for (int r = 0; r < 16; r++) {
            u64 rr = (r & M) ? r1 : r0;
            u64 ii = (r & M) ? i1 : i0;
            a[r] = fma2(ii, swap2(a[r]), mul2(rr, a[r]));
        }
    } else {
        int bit = (lane >> B) & 1;
        u64 rr = bit ? r1 : r0, ii = bit ? i1 : i0;
#pragma unroll
        for (int r = 0; r < 16; r++)
            a[r] = fma2(ii, swap2(a[r]), mul2(rr, a[r]));
    }
}

// ------------------------- multi-qubit gates --------------------------------

// Controlled-X: flip bit T where all CM bits set. CM==0 -> plain X.
template<int T, int CM>
__device__ __forceinline__ void g_cx(u64 a[16], int lane) {
    constexpr int CML = CM & ((1 << LB) - 1);
    constexpr int CMR = (CM >> LB) & 15;
    bool lp = ((lane & CML) == CML);
    if constexpr (T < LB) {
#pragma unroll
        for (int r = 0; r < 16; r++) {
            if ((r & CMR) == CMR) {
                u64 p = shfl2<(1 << T)>(a[r]);
                if constexpr (CML == 0) a[r] = p;
                else a[r] = lp ? p : a[r];
            }
        }
    } else {
        constexpr int MT = 1 << (T - LB);
#pragma unroll
        for (int r = 0; r < 16; r++) {
            if (((r & CMR) == CMR) && !(r & MT)) {
                int r1 = r | MT;
                u64 v0 = a[r], v1 = a[r1];
                if constexpr (CML == 0) { a[r] = v1; a[r1] = v0; }
                else { a[r] = lp ? v1 : v0; a[r1] = lp ? v0 : v1; }
            }
        }
    }
}

// CZ on bits BA, BB
template<int BA, int BB>
__device__ __forceinline__ void g_cz(u64 a[16], int lane) {
    bool lp = true;
    if constexpr (BA < LB) lp = lp && (((lane >> BA) & 1) != 0);
    if constexpr (BB < LB) lp = lp && (((lane >> BB) & 1) != 0);
    u64 sg = dup2(lp ? -1.f : 1.f);
#pragma unroll
    for (int r = 0; r < 16; r++) {
        bool rp = true;
        if (BA >= LB) rp = rp && (((r >> (BA - LB)) & 1) != 0);
        if (BB >= LB) rp = rp && (((r >> (BB - LB)) & 1) != 0);
        if (rp) a[r] = mul2(sg, a[r]);
    }
}

// Static prune: no swap possible for this r.
template<int A, int Bb, int C>
__device__ __forceinline__ constexpr bool cswap_possible(int r) {
    bool possible = true;
    if (C >= LB && !((r >> (C - LB)) & 1)) possible = false;
    if (A >= LB && Bb >= LB &&
        (((r >> (A - LB)) & 1) == ((r >> (Bb - LB)) & 1))) possible = false;
    return possible;
}

// Swap condition for element (r, lane).
template<int A, int Bb, int C>
__device__ __forceinline__ bool cswap_cond(int r, int lane, bool lctl) {
    int ba = (A  < LB) ? ((lane >> A)  & 1) : ((r >> (A  - LB)) & 1);
    int bb = (Bb < LB) ? ((lane >> Bb) & 1) : ((r >> (Bb - LB)) & 1);
    bool ctl = (C < LB) ? lctl : (((r >> (C - LB)) & 1) != 0);
    return ctl && (ba != bb);
}

// CSWAP: control C; swap bits A,Bb where they differ. Three static shapes.
template<int A, int Bb, int C>
__device__ __forceinline__ void g_cswap(u64 a[16], int lane) {
    constexpr int M  = (1 << A) | (1 << Bb);
    constexpr int ML = M & ((1 << LB) - 1);
    constexpr int MR = (M >> LB) & 15;
    bool lctl = true;
    if constexpr (C < LB) lctl = (((lane >> C) & 1) != 0);

    if constexpr (MR == 0) {
#pragma unroll
        for (int r = 0; r < 16; r++) {
            if (cswap_possible<A, Bb, C>(r)) {
                u64 p = shfl2<ML>(a[r]);
                bool sw = cswap_cond<A, Bb, C>(r, lane, lctl);
                a[r] = sw ? p : a[r];
            }
        }
    } else if constexpr (ML != 0) {
#pragma unroll
        for (int r = 0; r < 16; r++) {
            if ((r & MR) == 0) {
                int r1 = r | MR;
                bool pos0 = cswap_possible<A, Bb, C>(r);
                bool pos1 = cswap_possible<A, Bb, C>(r | MR);
                u64 p0s = a[r1], p1s = a[r];     // read both before any write
                if (pos0) {
                    u64 p0 = shfl2<ML>(p0s);
                    bool sw0 = cswap_cond<A, Bb, C>(r, lane, lctl);
                    a[r] = sw0 ? p0 : a[r];
                }
                if (pos1) {
                    u64 p1 = shfl2<ML>(p1s);
                    bool sw1 = cswap_cond<A, Bb, C>(r1, lane, lctl);
                    a[r1] = sw1 ? p1 : a[r1];
                }
            }
        }
    } else {
        constexpr int MA = 1 << (A - LB);
        constexpr int MB = 1 << (Bb - LB);
#pragma unroll
        for (int r = 0; r < 16; r++) {
            if ((r & MA) != 0 && (r & MB) == 0) {   // bitA=1, bitB=0
                int r1 = r ^ MR;                    // bitA=0, bitB=1
                bool ctl = (C < LB) ? lctl : (((r >> (C - LB)) & 1) != 0);
                u64 t0 = a[r], t1 = a[r1];
                a[r]  = ctl ? t1 : t0;
                a[r1] = ctl ? t0 : t1;
            }
        }
    }
}

// ---------------------------------------------------------------------------
// Per-block gate table in SHARED memory (5.6KB), computed by threads 0..47.
// code bits [0:3) = q1: 0 none,1 diag,2 real,3 cplx,4 ry,5 ry+diag,6 ry+real,7 ry+cplx
// code bits [3:6) = multiq: 0 none, 1 CNOT, 2 CSWAP, 3 TOF, 4 CZ.
// ce entry order: 0=M00, 1=M01, 2=M10, 3=M11.
// ---------------------------------------------------------------------------
struct GateTab {
    ulonglong2 ce[192];     // CE form entries (r2, i2) per matrix element
    ulonglong2 raw[96];     // packed (re,im) rows for runtime RY folding
    float4 realmat[48];     // (A00r, A01r, A10r, A11r)
    int code[48];
};

struct C2 { float re, im; };
__device__ __forceinline__ C2 cxm(C2 a, C2 b) {
    C2 o; o.re = a.re * b.re - a.im * b.im; o.im = a.re * b.im + a.im * b.re; return o;
}
__device__ __forceinline__ C2 cxa(C2 a, C2 b) { C2 o; o.re = a.re + b.re; o.im = a.im + b.im; return o; }

// Fold gate chain for (layer,node) = (i>>3, i&7); write into shared tab.
__device__ void fold_gate(GateTab& tab, int i,
                          const float* __restrict__ qp,
                          const int* __restrict__ dry,
                          const int* __restrict__ drot,
                          const int* __restrict__ dg2) {
    int node = i & 7;
    int di = (i >> 3) * 4 + (node & 3);
    float s, c;
    __sincosf(0.5f * __ldg(&qp[i]), &s, &c);

    C2 A[2][2] = {{{1.f,0.f},{0.f,0.f}},{{0.f,0.f},{1.f,0.f}}};
    bool haveA = false;
    int rot = __ldg(&drot[di]);
    if (rot == 0) {
        A[0][0] = {c,0.f}; A[0][1] = {0.f,-s}; A[1][0] = {0.f,-s}; A[1][1] = {c,0.f};
        haveA = true;
    } else if (rot == 1) {
        A[0][0] = {c,0.f}; A[0][1] = {-s,0.f}; A[1][0] = {s,0.f};  A[1][1] = {c,0.f};
        haveA = true;
    } else if (rot == 2) {
        A[0][0] = {c,-s};  A[0][1] = {0.f,0.f}; A[1][0] = {0.f,0.f}; A[1][1] = {c,s};
        haveA = true;
    }
    int g2 = __ldg(&dg2[di]);
    if (g2 >= 1 && g2 <= 4) {
        const float rh = 0.70710678118654752440f;
        C2 G[2][2];
        if (g2 == 1) {
            G[0][0] = {rh,0.f}; G[0][1] = {rh,0.f}; G[1][0] = {rh,0.f}; G[1][1] = {-rh,0.f};
        } else if (g2 == 2) {
            G[0][0] = {0.f,0.f}; G[0][1] = {1.f,0.f}; G[1][0] = {1.f,0.f}; G[1][1] = {0.f,0.f};
        } else if (g2 == 3) {
            G[0][0] = {0.f,0.f}; G[0][1] = {0.f,-1.f}; G[1][0] = {0.f,1.f}; G[1][1] = {0.f,0.f};
        } else {
            G[0][0] = {1.f,0.f}; G[0][1] = {0.f,0.f}; G[1][0] = {0.f,0.f}; G[1][1] = {-1.f,0.f};
        }
        C2 R[2][2];
        for (int r = 0; r < 2; r++)
            for (int cc = 0; cc < 2; cc++)
                R[r][cc] = cxa(cxm(G[r][0], A[0][cc]), cxm(G[r][1], A[1][cc]));
        A[0][0] = R[0][0]; A[0][1] = R[0][1]; A[1][0] = R[1][0]; A[1][1] = R[1][1];
        haveA = true;
    }
    int atype = 0;
    if (haveA) {
        bool offd  = (A[0][1].re != 0.f) || (A[0][1].im != 0.f) ||
                     (A[1][0].re != 0.f) || (A[1][0].im != 0.f);
        bool anyim = (A[0][0].im != 0.f) || (A[0][1].im != 0.f) ||
                     (A[1][0].im != 0.f) || (A[1][1].im != 0.f);
        atype = offd ? (anyim ? 3 : 2) : 1;
    }
    int q1 = (__ldg(&dry[di]) & 1) ? (4 + atype) : atype;
    int mq = (g2 >= 5) ? (g2 - 4) : 0;
    tab.code[i] = q1 | (mq << 3);

    tab.raw[2 * i]     = make_ulonglong2(pack2(A[0][0].re, A[0][0].im),
                                         pack2(A[0][1].re, A[0][1].im));
    tab.raw[2 * i + 1] = make_ulonglong2(pack2(A[1][0].re, A[1][0].im),
                                         pack2(A[1][1].re, A[1][1].im));
    tab.ce[4 * i + 0] = make_ulonglong2(dup2(A[0][0].re), pack2(-A[0][0].im, A[0][0].im));
    tab.ce[4 * i + 1] = make_ulonglong2(dup2(A[0][1].re), pack2(-A[0][1].im, A[0][1].im));
    tab.ce[4 * i + 2] = make_ulonglong2(dup2(A[1][0].re), pack2(-A[1][0].im, A[1][0].im));
    tab.ce[4 * i + 3] = make_ulonglong2(dup2(A[1][1].re), pack2(-A[1][1].im, A[1][1].im));
    tab.realmat[i] = make_float4(A[0][0].re, A[0][1].re, A[1][0].re, A[1][1].re);
}

// ---------------------------------------------------------------------------

template<int NODE>
__device__ __forceinline__ void do_node(const GateTab& tab, u64 a[16], int lane,
                                        int layer, float fc_, float fs_) {
    constexpr int B  = 7 - NODE;
    constexpr int B1 = 7 - ((NODE + 1) & 7);
    constexpr int B2 = 7 - ((NODE + 2) & 7);
    const int idx = layer * 8 + NODE;

    int code = tab.code[idx];         // uniform LDS broadcast
    int q1 = code & 7;
    if (q1) {
        switch (q1) {
            case 1: {   // diag: zero shuffles
                ulonglong2 e0 = tab.ce[4 * idx];
                ulonglong2 e3 = tab.ce[4 * idx + 3];
                ap_diag_ce<B>(a, lane, e0.x, e0.y, e3.x, e3.y);
            } break;
            case 2: {   // real
                float4 m = tab.realmat[idx];
                ap_real<B>(a, lane, m.x, m.y, m.z, m.w);
            } break;
            case 3: {   // complex
                if constexpr (B >= LB) {
                    ulonglong2 e0 = tab.ce[4 * idx + 0];
                    ulonglong2 e1 = tab.ce[4 * idx + 1];
                    ulonglong2 e2 = tab.ce[4 * idx + 2];
                    ulonglong2 e3 = tab.ce[4 * idx + 3];
                    ap_cplx_reg<B>(a, e0.x, e0.y, e1.x, e1.y,
                                      e2.x, e2.y, e3.x, e3.y);
                } else {
                    // SELECT-BEFORE-LOAD: U = M[bit][bit] (entry 3*bit),
                    // V = M[bit][1-bit] (entry 1+bit). 2 LDS.128 instead of 4.
                    int bit = (lane >> B) & 1;
                    ulonglong2 eu = tab.ce[4 * idx + 3 * bit];
                    ulonglong2 ev = tab.ce[4 * idx + 1 + bit];
                    ap_cplx_lane<B>(a, eu.x, eu.y, ev.x, ev.y);
                }
            } break;
            case 4: {   // pure RY — width-16 broadcast picks this half-warp's sample
                float c = __shfl_sync(FULLMASK, fc_, NODE, 16);
                float s = __shfl_sync(FULLMASK, fs_, NODE, 16);
                ap_real<B>(a, lane, c, -s, s, c);
            } break;
            case 6: {   // RY folded into real A
                float c = __shfl_sync(FULLMASK, fc_, NODE, 16);
                float s = __shfl_sync(FULLMASK, fs_, NODE, 16);
                float4 m = tab.realmat[idx];
                float u00 = fmaf(m.x, c,  m.y * s);
                float u01 = fmaf(m.y, c, -m.x * s);
                float u10 = fmaf(m.z, c,  m.w * s);
                float u11 = fmaf(m.w, c, -m.z * s);
                ap_real<B>(a, lane, u00, u01, u10, u11);
            } break;
            default: {  // 5 or 7: RY folded into complex A
                float c = __shfl_sync(FULLMASK, fc_, NODE, 16);
                float s = __shfl_sync(FULLMASK, fs_, NODE, 16);
                u64 c2 = dup2(c), s2 = dup2(s), ns2 = dup2(-s);
                if constexpr (B >= LB) {
                    ulonglong2 ra = tab.raw[2 * idx];
                    ulonglong2 rb = tab.raw[2 * idx + 1];
                    u64 M00 = fma2(s2, ra.y, mul2(c2,  ra.x));
                    u64 M01 = fma2(c2, ra.y, mul2(ns2, ra.x));
                    u64 M10 = fma2(s2, rb.y, mul2(c2,  rb.x));
                    u64 M11 = fma2(c2, rb.y, mul2(ns2, rb.x));
                    float mr, mi;
                    unpack2(M00, mr, mi); u64 r00 = dup2(mr), i00 = pack2(-mi, mi);
                    unpack2(M01, mr, mi); u64 r01 = dup2(mr), i01 = pack2(-mi, mi);
                    unpack2(M10, mr, mi); u64 r10 = dup2(mr), i10 = pack2(-mi, mi);
                    unpack2(M11, mr, mi); u64 r11 = dup2(mr), i11 = pack2(-mi, mi);
                    ap_cplx_reg<B>(a, r00, i00, r01, i01, r10, i10, r11, i11);
                } else {
                    // SELECT-BEFORE-FOLD: both needed entries are in row `bit`
                    // of M = A*RY. Load only that A row, fold 2 entries.
                    int bit = (lane >> B) & 1;
                    ulonglong2 row = tab.raw[2 * idx + bit];   // (A[bit][0], A[bit][1])
                    u64 Mi0 = fma2(s2, row.y, mul2(c2,  row.x));   // M[bit][0]
                    u64 Mi1 = fma2(c2, row.y, mul2(ns2, row.x));   // M[bit][1]
                    u64 Mu = bit ? Mi1 : Mi0;   // M[bit][bit]
                    u64 Mv = bit ? Mi0 : Mi1;   // M[bit][1-bit]
                    float mr, mi;
                    unpack2(Mu, mr, mi); u64 ur = dup2(mr), ui = pack2(-mi, mi);
                    unpack2(Mv, mr, mi); u64 vr = dup2(mr), vi = pack2(-mi, mi);
                    ap_cplx_lane<B>(a, ur, ui, vr, vi);
                }
            } break;
        }
    }
    int mq = (code >> 3) & 7;
    if (mq) {
        switch (mq) {
            case 1: g_cx<B1, (1 << B)>(a, lane); break;               // CNOT
            case 2: g_cswap<B1, B2, B>(a, lane); break;               // CSWAP
            case 3: g_cx<B2, (1 << B) | (1 << B1)>(a, lane); break;   // Toffoli
            default: g_cz<B, B1>(a, lane); break;                     // CZ
        }
    }
}

__global__ void __launch_bounds__(256, 4) qsim_kernel(
    const float* __restrict__ feats,   // [B, 8]
    const float* __restrict__ qp,      // [48]
    const int* __restrict__ dry,       // [24]
    const int* __restrict__ drot,      // [24]
    const int* __restrict__ dg2,       // [24]
    float* __restrict__ out,           // [B, 8]
    int nwarps) {
    __shared__ GateTab tab;
    if (threadIdx.x < 48)
        fold_gate(tab, threadIdx.x, qp, dry, drot, dg2);

    int w = (int)((blockIdx.x * blockDim.x + threadIdx.x) >> 5);
    int lane = threadIdx.x & 31;

    int sample = 2 * w + (lane >> 4);       // half-warp's sample
    float fv = 0.f;
    if (w < nwarps) fv = feats[sample * 8 + (lane & 7)];
    float fs_, fc_;
    __sincosf(0.5f * fv, &fs_, &fc_);

    __syncthreads();                        // table ready
    if (w >= nwarps) return;

    // H^8 |0...0>  ==  uniform 1/16 real amplitude
    u64 a[16];
    u64 init = pack2(0.0625f, 0.0f);
#pragma unroll
    for (int r = 0; r < 16; r++) a[r] = init;

#pragma unroll 1
    for (int layer = 0; layer < 6; ++layer) {
        do_node<0>(tab, a, lane, layer, fc_, fs_);
        do_node<1>(tab, a, lane, layer, fc_, fs_);
        do_node<2>(tab, a, lane, layer, fc_, fs_);
        do_node<3>(tab, a, lane, layer, fc_, fs_);
        do_node<4>(tab, a, lane, layer, fc_, fs_);
        do_node<5>(tab, a, lane, layer, fc_, fs_);
        do_node<6>(tab, a, lane, layer, fc_, fs_);
        do_node<7>(tab, a, lane, layer, fc_, fs_);
    }

    // <Z_p> = sum_i |a_i|^2 * (1 - 2*bit_{7-p}(i)),  i = (r<<4) | (lane&15)
    float acc[8];
#pragma unroll
    for (int p = 0; p < 8; p++) acc[p] = 0.f;
    float sgl[8];
#pragma unroll
    for (int p = 4; p < 8; p++)
        sgl[p] = ((lane >> (7 - p)) & 1) ? -1.f : 1.f;   // lane bits 3..0
#pragma unroll
    for (int r = 0; r < 16; r++) {
        float re, im;
        unpack2(a[r], re, im);
        float pr = fmaf(re, re, im * im);
        // p=0..3 -> bits 7..4 -> r bits 3..0: compile-time signs
        acc[0] += ((r >> 3) & 1) ? -pr : pr;
        acc[1] += ((r >> 2) & 1) ? -pr : pr;
        acc[2] += ((r >> 1) & 1) ? -pr : pr;
        acc[3] += (r & 1)        ? -pr : pr;
#pragma unroll
        for (int p = 4; p < 8; p++) acc[p] += sgl[p] * pr;
    }
#pragma unroll
    for (int p = 0; p < 8; p++) {
#pragma unroll
        for (int off = 8; off; off >>= 1)   // width-16 butterfly
            acc[p] += __shfl_xor_sync(FULLMASK, acc[p], off);
    }
    if ((lane & 15) == 0) {
        float4* o = reinterpret_cast<float4*>(out + (size_t)sample * 8);
        o[0] = make_float4(acc[0], acc[1], acc[2], acc[3]);
        o[1] = make_float4(acc[4], acc[5], acc[6], acc[7]);
    }
}

extern "C" void kernel_launch(void* const* d_in, const int* in_sizes, int n_in,
                              void* d_out, int out_size) {
    const float* feats = (const float*)d_in[0];   // [B, 8] float32
    const float* qp    = (const float*)d_in[1];   // [48]  float32
    const int* dry     = (const int*)d_in[2];     // [6,4] int32
    const int* drot    = (const int*)d_in[3];     // [6,4] int32
    const int* dg2     = (const int*)d_in[4];     // [6,4] int32
    float* out         = (float*)d_out;           // [B, 8] float32

    int batch = in_sizes[0] / 8;
    int nwarps = batch / 2;                       // 2 samples per warp

    int threads = 256;
    long long total_threads = (long long)nwarps * 32;
    int blocks = (int)((total_threads + threads - 1) / threads);
    qsim_kernel<<<blocks, threads>>>(feats, qp, dry, drot, dg2, out, nwarps);
}

// round 17
// speedup vs baseline: 1.1226x; 1.0221x over previous
#include <cuda_runtime.h>

#define FULLMASK 0xffffffffu
typedef unsigned long long u64;

// ---------------------------------------------------------------------------
// TWO SAMPLES PER WARP — SINGLE KERNEL LAUNCH. (R16 base, best = 85.9us)
// Amplitude index i (8 bits) = (r << 4) | (lane & 15). Sample = 2*warp + lane>>4.
// wire w <-> bit (7-w). Bits 0..3 = lane bits, 4..7 = register bits.
// a[16] packed complex amplitudes (lo32=re, hi32=im).
// R17: (1) per-layer code prefetch (two LDS.128 instead of eight LDS.32,
// dispatch predicates ready ahead of use); (2) real gates load CE-form
// coefficients directly from shared (kills dup2/SEL MOV chains).
// ---------------------------------------------------------------------------

constexpr int LB = 4;   // number of lane bits

__device__ __forceinline__ u64 pack2(float lo, float hi) {
    u64 r; asm("mov.b64 %0, {%1, %2};" : "=l"(r) : "f"(lo), "f"(hi)); return r;
}
__device__ __forceinline__ void unpack2(u64 v, float& lo, float& hi) {
    asm("mov.b64 {%0, %1}, %2;" : "=f"(lo), "=f"(hi) : "l"(v));
}
__device__ __forceinline__ u64 dup2(float x) { return pack2(x, x); }
__device__ __forceinline__ u64 fma2(u64 a, u64 b, u64 c) {
    u64 d; asm("fma.rn.f32x2 %0, %1, %2, %3;" : "=l"(d) : "l"(a), "l"(b), "l"(c)); return d;
}
__device__ __forceinline__ u64 mul2(u64 a, u64 b) {
    u64 d; asm("mul.rn.f32x2 %0, %1, %2;" : "=l"(d) : "l"(a), "l"(b)); return d;
}
__device__ __forceinline__ u64 swap2(u64 v) {
    float lo, hi; unpack2(v, lo, hi); return pack2(hi, lo);
}
template<int ML>
__device__ __forceinline__ u64 shfl2(u64 v) {
    float lo, hi; unpack2(v, lo, hi);
    lo = __shfl_xor_sync(FULLMASK, lo, ML);
    hi = __shfl_xor_sync(FULLMASK, hi, ML);
    return pack2(lo, hi);
}

// ------------------------- fused 1q applies ---------------------------------

// Real 2x2 with PACKED coefficients (already in dup2 form).
template<int B>
__device__ __forceinline__ void ap_real_pk(u64 a[16], u64 c00, u64 c01,
                                           u64 c10, u64 c11) {
    static_assert(B >= LB, "reg path only");
    constexpr int M = 1 << (B - LB);
#pragma unroll
    for (int r = 0; r < 16; r++) {
        if ((r & M) == 0) {
            int r1 = r | M;
            u64 v0 = a[r], v1 = a[r1];
            a[r]  = fma2(c01, v1, mul2(c00, v0));
            a[r1] = fma2(c11, v1, mul2(c10, v0));
        }
    }
}

// Real 2x2 lane-bit apply with pre-selected packed coefficients u, v.
template<int B>
__device__ __forceinline__ void ap_real_lane_pk(u64 a[16], u64 u, u64 v) {
    static_assert(B < LB, "lane path only");
#pragma unroll
    for (int r = 0; r < 16; r++) {
        u64 p = shfl2<(1 << B)>(a[r]);
        a[r] = fma2(v, p, mul2(u, a[r]));
    }
}

// Real 2x2 from scalar coefficients (RY / folded paths).
template<int B>
__device__ __forceinline__ void ap_real(u64 a[16], int lane,
                                        float u00, float u01, float u10, float u11) {
    if constexpr (B >= LB) {
        ap_real_pk<B>(a, dup2(u00), dup2(u01), dup2(u10), dup2(u11));
    } else {
        int bit = (lane >> B) & 1;
        u64 u = dup2(bit ? u11 : u00);
        u64 v = dup2(bit ? u10 : u01);
        ap_real_lane_pk<B>(a, u, v);
    }
}

// Complex 2x2 full (register-bit wires only), CE form per entry.
template<int B>
__device__ __forceinline__ void ap_cplx_reg(u64 a[16],
        u64 r00, u64 i00, u64 r01, u64 i01,
        u64 r10, u64 i10, u64 r11, u64 i11) {
    static_assert(B >= LB, "reg path only");
    constexpr int M = 1 << (B - LB);
#pragma unroll
    for (int r = 0; r < 16; r++) {
        if ((r & M) == 0) {
            int r1 = r | M;
            u64 v0 = a[r], v1 = a[r1];
            u64 s0 = swap2(v0), s1 = swap2(v1);
            a[r]  = fma2(i01, s1, fma2(r01, v1, fma2(i00, s0, mul2(r00, v0))));
            a[r1] = fma2(i11, s1, fma2(r11, v1, fma2(i10, s0, mul2(r10, v0))));
        }
    }
}

// Complex 2x2 lane-bit apply with PRE-SELECTED entries (this thread's row):
// U = M[bit][bit], V = M[bit][1-bit], CE form.
template<int B>
__device__ __forceinline__ void ap_cplx_lane(u64 a[16],
        u64 ur, u64 ui, u64 vr, u64 vi) {
    static_assert(B < LB, "lane path only");
#pragma unroll
    for (int r = 0; r < 16; r++) {
        u64 p = shfl2<(1 << B)>(a[r]);
        u64 t = fma2(ui, swap2(a[r]), mul2(ur, a[r]));
        a[r] = fma2(vi, swap2(p), fma2(vr, p, t));
    }
}

// Diagonal complex (CE form d0, d1) — zero shuffles.
template<int B>
__device__ __forceinline__ void ap_diag_ce(u64 a[16], int lane,
                                           u64 r0, u64 i0, u64 r1, u64 i1) {
    if constexpr (B >= LB) {
        constexpr int M = 1 << (B - LB);
#pragma unroll
        for (int r = 0; r < 16; r++) {
            u64 rr = (r & M) ? r1 : r0;
            u64 ii = (r & M) ? i1 : i0;
            a[r] = fma2(ii, swap2(a[r]), mul2(rr, a[r]));
        }
    } else {
        int bit = (lane >> B) & 1;
        u64 rr = bit ? r1 : r0, ii = bit ? i1 : i0;
#pragma unroll
        for (int r = 0; r < 16; r++)
            a[r] = fma2(ii, swap2(a[r]), mul2(rr, a[r]));
    }
}

// ------------------------- multi-qubit gates --------------------------------

// Controlled-X: flip bit T where all CM bits set. CM==0 -> plain X.
template<int T, int CM>
__device__ __forceinline__ void g_cx(u64 a[16], int lane) {
    constexpr int CML = CM & ((1 << LB) - 1);
    constexpr int CMR = (CM >> LB) & 15;
    bool lp = ((lane & CML) == CML);
    if constexpr (T < LB) {
#pragma unroll
        for (int r = 0; r < 16; r++) {
            if ((r & CMR) == CMR) {
                u64 p = shfl2<(1 << T)>(a[r]);
                if constexpr (CML == 0) a[r] = p;
                else a[r] = lp ? p : a[r];
            }
        }
    } else {
        constexpr int MT = 1 << (T - LB);
#pragma unroll
        for (int r = 0; r < 16; r++) {
            if (((r & CMR) == CMR) && !(r & MT)) {
                int r1 = r | MT;
                u64 v0 = a[r], v1 = a[r1];
                if constexpr (CML == 0) { a[r] = v1; a[r1] = v0; }
                else { a[r] = lp ? v1 : v0; a[r1] = lp ? v0 : v1; }
            }
        }
    }
}

// CZ on bits BA, BB
template<int BA, int BB>
__device__ __forceinline__ void g_cz(u64 a[16], int lane) {
    bool lp = true;
    if constexpr (BA < LB) lp = lp && (((lane >> BA) & 1) != 0);
    if constexpr (BB < LB) lp = lp && (((lane >> BB) & 1) != 0);
    u64 sg = dup2(lp ? -1.f : 1.f);
#pragma unroll
    for (int r = 0; r < 16; r++) {
        bool rp = true;
        if (BA >= LB) rp = rp && (((r >> (BA - LB)) & 1) != 0);
        if (BB >= LB) rp = rp && (((r >> (BB - LB)) & 1) != 0);
        if (rp) a[r] = mul2(sg, a[r]);
    }
}

// Static prune: no swap possible for this r.
template<int A, int Bb, int C>
__device__ __forceinline__ constexpr bool cswap_possible(int r) {
    bool possible = true;
    if (C >= LB && !((r >> (C - LB)) & 1)) possible = false;
    if (A >= LB && Bb >= LB &&
        (((r >> (A - LB)) & 1) == ((r >> (Bb - LB)) & 1))) possible = false;
    return possible;
}

// Swap condition for element (r, lane).
template<int A, int Bb, int C>
__device__ __forceinline__ bool cswap_cond(int r, int lane, bool lctl) {
    int ba = (A  < LB) ? ((lane >> A)  & 1) : ((r >> (A  - LB)) & 1);
    int bb = (Bb < LB) ? ((lane >> Bb) & 1) : ((r >> (Bb - LB)) & 1);
    bool ctl = (C < LB) ? lctl : (((r >> (C - LB)) & 1) != 0);
    return ctl && (ba != bb);
}

// CSWAP: control C; swap bits A,Bb where they differ. Three static shapes.
template<int A, int Bb, int C>
__device__ __forceinline__ void g_cswap(u64 a[16], int lane) {
    constexpr int M  = (1 << A) | (1 << Bb);
    constexpr int ML = M & ((1 << LB) - 1);
    constexpr int MR = (M >> LB) & 15;
    bool lctl = true;
    if constexpr (C < LB) lctl = (((lane >> C) & 1) != 0);

    if constexpr (MR == 0) {
#pragma unroll
        for (int r = 0; r < 16; r++) {
            if (cswap_possible<A, Bb, C>(r)) {
                u64 p = shfl2<ML>(a[r]);
                bool sw = cswap_cond<A, Bb, C>(r, lane, lctl);
                a[r] = sw ? p : a[r];
            }
        }
    } else if constexpr (ML != 0) {
#pragma unroll
        for (int r = 0; r < 16; r++) {
            if ((r & MR) == 0) {
                int r1 = r | MR;
                bool pos0 = cswap_possible<A, Bb, C>(r);
                bool pos1 = cswap_possible<A, Bb, C>(r | MR);
                u64 p0s = a[r1], p1s = a[r];     // read both before any write
                if (pos0) {
                    u64 p0 = shfl2<ML>(p0s);
                    bool sw0 = cswap_cond<A, Bb, C>(r, lane, lctl);
                    a[r] = sw0 ? p0 : a[r];
                }
                if (pos1) {
                    u64 p1 = shfl2<ML>(p1s);
                    bool sw1 = cswap_cond<A, Bb, C>(r1, lane, lctl);
                    a[r1] = sw1 ? p1 : a[r1];
                }
            }
        }
    } else {
        constexpr int MA = 1 << (A - LB);
        constexpr int MB = 1 << (Bb - LB);
#pragma unroll
        for (int r = 0; r < 16; r++) {
            if ((r & MA) != 0 && (r & MB) == 0) {   // bitA=1, bitB=0
                int r1 = r ^ MR;                    // bitA=0, bitB=1
                bool ctl = (C < LB) ? lctl : (((r >> (C - LB)) & 1) != 0);
                u64 t0 = a[r], t1 = a[r1];
                a[r]  = ctl ? t1 : t0;
                a[r1] = ctl ? t0 : t1;
            }
        }
    }
}

// ---------------------------------------------------------------------------
// Per-block gate table in SHARED memory (5.6KB), computed by threads 0..47.
// code bits [0:3) = q1: 0 none,1 diag,2 real,3 cplx,4 ry,5 ry+diag,6 ry+real,7 ry+cplx
// code bits [3:6) = multiq: 0 none, 1 CNOT, 2 CSWAP, 3 TOF, 4 CZ.
// ce entry order: 0=M00, 1=M01, 2=M10, 3=M11 (r2 = dup2(re), i2 = (-im,im)).
// ---------------------------------------------------------------------------
struct GateTab {
    ulonglong2 ce[192];     // CE form entries (r2, i2) per matrix element
    ulonglong2 raw[96];     // packed (re,im) rows for runtime RY folding
    float4 realmat[48];     // (A00r, A01r, A10r, A11r)
    int code[48];           // 16B-aligned (offset 5376)
};

struct C2 { float re, im; };
__device__ __forceinline__ C2 cxm(C2 a, C2 b) {
    C2 o; o.re = a.re * b.re - a.im * b.im; o.im = a.re * b.im + a.im * b.re; return o;
}
__device__ __forceinline__ C2 cxa(C2 a, C2 b) { C2 o; o.re = a.re + b.re; o.im = a.im + b.im; return o; }

// Fold gate chain for (layer,node) = (i>>3, i&7); write into shared tab.
__device__ void fold_gate(GateTab& tab, int i,
                          const float* __restrict__ qp,
                          const int* __restrict__ dry,
                          const int* __restrict__ drot,
                          const int* __restrict__ dg2) {
    int node = i & 7;
    int di = (i >> 3) * 4 + (node & 3);
    float s, c;
    __sincosf(0.5f * __ldg(&qp[i]), &s, &c);

    C2 A[2][2] = {{{1.f,0.f},{0.f,0.f}},{{0.f,0.f},{1.f,0.f}}};
    bool haveA = false;
    int rot = __ldg(&drot[di]);
    if (rot == 0) {
        A[0][0] = {c,0.f}; A[0][1] = {0.f,-s}; A[1][0] = {0.f,-s}; A[1][1] = {c,0.f};
        haveA = true;
    } else if (rot == 1) {
        A[0][0] = {c,0.f}; A[0][1] = {-s,0.f}; A[1][0] = {s,0.f};  A[1][1] = {c,0.f};
        haveA = true;
    } else if (rot == 2) {
        A[0][0] = {c,-s};  A[0][1] = {0.f,0.f}; A[1][0] = {0.f,0.f}; A[1][1] = {c,s};
        haveA = true;
    }
    int g2 = __ldg(&dg2[di]);
    if (g2 >= 1 && g2 <= 4) {
        const float rh = 0.70710678118654752440f;
        C2 G[2][2];
        if (g2 == 1) {
            G[0][0] = {rh,0.f}; G[0][1] = {rh,0.f}; G[1][0] = {rh,0.f}; G[1][1] = {-rh,0.f};
        } else if (g2 == 2) {
            G[0][0] = {0.f,0.f}; G[0][1] = {1.f,0.f}; G[1][0] = {1.f,0.f}; G[1][1] = {0.f,0.f};
        } else if (g2 == 3) {
            G[0][0] = {0.f,0.f}; G[0][1] = {0.f,-1.f}; G[1][0] = {0.f,1.f}; G[1][1] = {0.f,0.f};
        } else {
            G[0][0] = {1.f,0.f}; G[0][1] = {0.f,0.f}; G[1][0] = {0.f,0.f}; G[1][1] = {-1.f,0.f};
        }
        C2 R[2][2];
        for (int r = 0; r < 2; r++)
            for (int cc = 0; cc < 2; cc++)
                R[r][cc] = cxa(cxm(G[r][0], A[0][cc]), cxm(G[r][1], A[1][cc]));
        A[0][0] = R[0][0]; A[0][1] = R[0][1]; A[1][0] = R[1][0]; A[1][1] = R[1][1];
        haveA = true;
    }
    int atype = 0;
    if (haveA) {
        bool offd  = (A[0][1].re != 0.f) || (A[0][1].im != 0.f) ||
                     (A[1][0].re != 0.f) || (A[1][0].im != 0.f);
        bool anyim = (A[0][0].im != 0.f) || (A[0][1].im != 0.f) ||
                     (A[1][0].im != 0.f) || (A[1][1].im != 0.f);
        atype = offd ? (anyim ? 3 : 2) : 1;
    }
    int q1 = (__ldg(&dry[di]) & 1) ? (4 + atype) : atype;
    int mq = (g2 >= 5) ? (g2 - 4) : 0;
    tab.code[i] = q1 | (mq << 3);

    tab.raw[2 * i]     = make_ulonglong2(pack2(A[0][0].re, A[0][0].im),
                                         pack2(A[0][1].re, A[0][1].im));
    tab.raw[2 * i + 1] = make_ulonglong2(pack2(A[1][0].re, A[1][0].im),
                                         pack2(A[1][1].re, A[1][1].im));
    tab.ce[4 * i + 0] = make_ulonglong2(dup2(A[0][0].re), pack2(-A[0][0].im, A[0][0].im));
    tab.ce[4 * i + 1] = make_ulonglong2(dup2(A[0][1].re), pack2(-A[0][1].im, A[0][1].im));
    tab.ce[4 * i + 2] = make_ulonglong2(dup2(A[1][0].re), pack2(-A[1][0].im, A[1][0].im));
    tab.ce[4 * i + 3] = make_ulonglong2(dup2(A[1][1].re), pack2(-A[1][1].im, A[1][1].im));
    tab.realmat[i] = make_float4(A[0][0].re, A[0][1].re, A[1][0].re, A[1][1].re);
}

// ---------------------------------------------------------------------------

template<int NODE>
__device__ __forceinline__ void do_node(const GateTab& tab, u64 a[16], int lane,
                                        int layer, float fc_, float fs_,
                                        int code) {
    constexpr int B  = 7 - NODE;
    constexpr int B1 = 7 - ((NODE + 1) & 7);
    constexpr int B2 = 7 - ((NODE + 2) & 7);
    const int idx = layer * 8 + NODE;

    int q1 = code & 7;
    if (q1) {
        switch (q1) {
            case 1: {   // diag: zero shuffles
                ulonglong2 e0 = tab.ce[4 * idx];
                ulonglong2 e3 = tab.ce[4 * idx + 3];
                ap_diag_ce<B>(a, lane, e0.x, e0.y, e3.x, e3.y);
            } break;
            case 2: {   // real: CE .x entries are already dup2(re)
                if constexpr (B >= LB) {
                    u64 c00 = tab.ce[4 * idx + 0].x;
                    u64 c01 = tab.ce[4 * idx + 1].x;
                    u64 c10 = tab.ce[4 * idx + 2].x;
                    u64 c11 = tab.ce[4 * idx + 3].x;
                    ap_real_pk<B>(a, c00, c01, c10, c11);
                } else {
                    int bit = (lane >> B) & 1;
                    u64 u = tab.ce[4 * idx + 3 * bit].x;   // M[bit][bit]
                    u64 v = tab.ce[4 * idx + 1 + bit].x;   // M[bit][1-bit]
                    ap_real_lane_pk<B>(a, u, v);
                }
            } break;
            case 3: {   // complex
                if constexpr (B >= LB) {
                    ulonglong2 e0 = tab.ce[4 * idx + 0];
                    ulonglong2 e1 = tab.ce[4 * idx + 1];
                    ulonglong2 e2 = tab.ce[4 * idx + 2];
                    ulonglong2 e3 = tab.ce[4 * idx + 3];
                    ap_cplx_reg<B>(a, e0.x, e0.y, e1.x, e1.y,
                                      e2.x, e2.y, e3.x, e3.y);
                } else {
                    int bit = (lane >> B) & 1;
                    ulonglong2 eu = tab.ce[4 * idx + 3 * bit];
                    ulonglong2 ev = tab.ce[4 * idx + 1 + bit];
                    ap_cplx_lane<B>(a, eu.x, eu.y, ev.x, ev.y);
                }
            } break;
            case 4: {   // pure RY — width-16 broadcast picks this half-warp's sample
                float c = __shfl_sync(FULLMASK, fc_, NODE, 16);
                float s = __shfl_sync(FULLMASK, fs_, NODE, 16);
                ap_real<B>(a, lane, c, -s, s, c);
            } break;
            case 6: {   // RY folded into real A
                float c = __shfl_sync(FULLMASK, fc_, NODE, 16);
                float s = __shfl_sync(FULLMASK, fs_, NODE, 16);
                float4 m = tab.realmat[idx];
                float u00 = fmaf(m.x, c,  m.y * s);
                float u01 = fmaf(m.y, c, -m.x * s);
                float u10 = fmaf(m.z, c,  m.w * s);
                float u11 = fmaf(m.w, c, -m.z * s);
                ap_real<B>(a, lane, u00, u01, u10, u11);
            } break;
            default: {  // 5 or 7: RY folded into complex A
                float c = __shfl_sync(FULLMASK, fc_, NODE, 16);
                float s = __shfl_sync(FULLMASK, fs_, NODE, 16);
                u64 c2 = dup2(c), s2 = dup2(s), ns2 = dup2(-s);
                if constexpr (B >= LB) {
                    ulonglong2 ra = tab.raw[2 * idx];
                    ulonglong2 rb = tab.raw[2 * idx + 1];
                    u64 M00 = fma2(s2, ra.y, mul2(c2,  ra.x));
                    u64 M01 = fma2(c2, ra.y, mul2(ns2, ra.x));
                    u64 M10 = fma2(s2, rb.y, mul2(c2,  rb.x));
                    u64 M11 = fma2(c2, rb.y, mul2(ns2, rb.x));
                    float mr, mi;
                    unpack2(M00, mr, mi); u64 r00 = dup2(mr), i00 = pack2(-mi, mi);
                    unpack2(M01, mr, mi); u64 r01 = dup2(mr), i01 = pack2(-mi, mi);
                    unpack2(M10, mr, mi); u64 r10 = dup2(mr), i10 = pack2(-mi, mi);
                    unpack2(M11, mr, mi); u64 r11 = dup2(mr), i11 = pack2(-mi, mi);
                    ap_cplx_reg<B>(a, r00, i00, r01, i01, r10, i10, r11, i11);
                } else {
                    // SELECT-BEFORE-FOLD: both needed entries in row `bit`.
                    int bit = (lane >> B) & 1;
                    ulonglong2 row = tab.raw[2 * idx + bit];   // (A[bit][0], A[bit][1])
                    u64 Mi0 = fma2(s2, row.y, mul2(c2,  row.x));   // M[bit][0]
                    u64 Mi1 = fma2(c2, row.y, mul2(ns2, row.x));   // M[bit][1]
                    u64 Mu = bit ? Mi1 : Mi0;   // M[bit][bit]
                    u64 Mv = bit ? Mi0 : Mi1;   // M[bit][1-bit]
                    float mr, mi;
                    unpack2(Mu, mr, mi); u64 ur = dup2(mr), ui = pack2(-mi, mi);
                    unpack2(Mv, mr, mi); u64 vr = dup2(mr), vi = pack2(-mi, mi);
                    ap_cplx_lane<B>(a, ur, ui, vr, vi);
                }
            } break;
        }
    }
    int mq = (code >> 3) & 7;
    if (mq) {
        switch (mq) {
            case 1: g_cx<B1, (1 << B)>(a, lane); break;               // CNOT
            case 2: g_cswap<B1, B2, B>(a, lane); break;               // CSWAP
            case 3: g_cx<B2, (1 << B) | (1 << B1)>(a, lane); break;   // Toffoli
            default: g_cz<B, B1>(a, lane); break;                     // CZ
        }
    }
}

__global__ void __launch_bounds__(256, 4) qsim_kernel(
    const float* __restrict__ feats,   // [B, 8]
    const float* __restrict__ qp,      // [48]
    const int* __restrict__ dry,       // [24]
    const int* __restrict__ drot,      // [24]
    const int* __restrict__ dg2,       // [24]
    float* __restrict__ out,           // [B, 8]
    int nwarps) {
    __shared__ GateTab tab;
    if (threadIdx.x < 48)
        fold_gate(tab, threadIdx.x, qp, dry, drot, dg2);

    int w = (int)((blockIdx.x * blockDim.x + threadIdx.x) >> 5);
    int lane = threadIdx.x & 31;

    int sample = 2 * w + (lane >> 4);       // half-warp's sample
    float fv = 0.f;
    if (w < nwarps) fv = feats[sample * 8 + (lane & 7)];
    float fs_, fc_;
    __sincosf(0.5f * fv, &fs_, &fc_);

    __syncthreads();                        // table ready
    if (w >= nwarps) return;

    // H^8 |0...0>  ==  uniform 1/16 real amplitude
    u64 a[16];
    u64 init = pack2(0.0625f, 0.0f);
#pragma unroll
    for (int r = 0; r < 16; r++) a[r] = init;

#pragma unroll 1
    for (int layer = 0; layer < 6; ++layer) {
        // Prefetch the 8 node codes for this layer (two LDS.128).
        const int4* cp = reinterpret_cast<const int4*>(&tab.code[layer * 8]);
        int4 c03 = cp[0];
        int4 c47 = cp[1];
        do_node<0>(tab, a, lane, layer, fc_, fs_, c03.x);
        do_node<1>(tab, a, lane, layer, fc_, fs_, c03.y);
        do_node<2>(tab, a, lane, layer, fc_, fs_, c03.z);
        do_node<3>(tab, a, lane, layer, fc_, fs_, c03.w);
        do_node<4>(tab, a, lane, layer, fc_, fs_, c47.x);
        do_node<5>(tab, a, lane, layer, fc_, fs_, c47.y);
        do_node<6>(tab, a, lane, layer, fc_, fs_, c47.z);
        do_node<7>(tab, a, lane, layer, fc_, fs_, c47.w);
    }

    // <Z_p> = sum_i |a_i|^2 * (1 - 2*bit_{7-p}(i)),  i = (r<<4) | (lane&15)
    float acc[8];
#pragma unroll
    for (int p = 0; p < 8; p++) acc[p] = 0.f;
    float sgl[8];
#pragma unroll
    for (int p = 4; p < 8; p++)
        sgl[p] = ((lane >> (7 - p)) & 1) ? -1.f : 1.f;   // lane bits 3..0
#pragma unroll
    for (int r = 0; r < 16; r++) {
        float re, im;
        unpack2(a[r], re, im);
        float pr = fmaf(re, re, im * im);
        // p=0..3 -> bits 7..4 -> r bits 3..0: compile-time signs
        acc[0] += ((r >> 3) & 1) ? -pr : pr;
        acc[1] += ((r >> 2) & 1) ? -pr : pr;
        acc[2] += ((r >> 1) & 1) ? -pr : pr;
        acc[3] += (r & 1)        ? -pr : pr;
#pragma unroll
        for (int p = 4; p < 8; p++) acc[p] += sgl[p] * pr;
    }
#pragma unroll
    for (int p = 0; p < 8; p++) {
#pragma unroll
        for (int off = 8; off; off >>= 1)   // width-16 butterfly
            acc[p] += __shfl_xor_sync(FULLMASK, acc[p], off);
    }
    if ((lane & 15) == 0) {
        float4* o = reinterpret_cast<float4*>(out + (size_t)sample * 8);
        o[0] = make_float4(acc[0], acc[1], acc[2], acc[3]);
        o[1] = make_float4(acc[4], acc[5], acc[6], acc[7]);
    }
}

extern "C" void kernel_launch(void* const* d_in, const int* in_sizes, int n_in,
                              void* d_out, int out_size) {
    const float* feats = (const float*)d_in[0];   // [B, 8] float32
    const float* qp    = (const float*)d_in[1];   // [48]  float32
    const int* dry     = (const int*)d_in[2];     // [6,4] int32
    const int* drot    = (const int*)d_in[3];     // [6,4] int32
    const int* dg2     = (const int*)d_in[4];     // [6,4] int32
    float* out         = (float*)d_out;           // [B, 8] float32

    int batch = in_sizes[0] / 8;
    int nwarps = batch / 2;                       // 2 samples per warp

    int threads = 256;
    long long total_threads = (long long)nwarps * 32;
    int blocks = (int)((total_threads + threads - 1) / threads);
    qsim_kernel<<<blocks, threads>>>(feats, qp, dry, drot, dg2, out, nwarps);
}